// round 15
// baseline (speedup 1.0000x reference)
#include <cuda_runtime.h>
#include <cuda_fp16.h>
#include <math.h>
#include <stdint.h>

#define Cc 512
#define Bb 8
#define Nn 4096
#define GROUPS 8
#define EPS 1e-5f

#define MC ((size_t)Bb * Nn * Cc)
#define SC ((size_t)Bb * Nn * Nn)
#define NCs ((long long)Nn * Cc)
#define NNs ((long long)Nn * Nn)
#define NROWS (Bb * Nn)                 // 32768 attention rows

// ---------------- scratch ----------------
__device__ __half g_hh[MC];
__device__ __half g_w4h[4 * Cc * Cc];
__device__ __half g_qh[MC];
__device__ __half g_kh[MC];
__device__ __half g_vth[MC];
__device__ __half g_sh[SC];            // scores fp16 (scaled)
__device__ __half g_aoh[MC];
__device__ float2 g_red[32 * NROWS];   // [coltile][row] partial (max, sumexp)
__device__ float  g_mx[NROWS];
__device__ float  g_inv[NROWS];
__device__ float  g_stats[Bb * GROUPS * 2];
__device__ float  g_part[512 * 2];

// ---------------- 1) group-norm statistics (two-phase) ----------------
__global__ void gn_stats1_kernel(const float* __restrict__ x) {
    int blk = blockIdx.x;
    int bg = blk >> 3, sub = blk & 7;
    const size_t cnt = (size_t)(Cc / GROUPS) * Nn;
    const float4* p = (const float4*)(x + (size_t)bg * cnt + (size_t)sub * (cnt / 8));
    int tid = threadIdx.x;
    float s = 0.f, sq = 0.f;
    #pragma unroll 4
    for (int i = tid; i < (int)(cnt / 8 / 4); i += 256) {
        float4 v = p[i];
        s  += v.x + v.y + v.z + v.w;
        sq += v.x * v.x + v.y * v.y + v.z * v.z + v.w * v.w;
    }
    int lane = tid & 31, warp = tid >> 5;
    #pragma unroll
    for (int o = 16; o > 0; o >>= 1) {
        s  += __shfl_xor_sync(~0u, s, o);
        sq += __shfl_xor_sync(~0u, sq, o);
    }
    __shared__ float ss[8], ssq[8];
    if (lane == 0) { ss[warp] = s; ssq[warp] = sq; }
    __syncthreads();
    if (tid == 0) {
        float ts = 0.f, tq = 0.f;
        #pragma unroll
        for (int j = 0; j < 8; j++) { ts += ss[j]; tq += ssq[j]; }
        g_part[blk * 2 + 0] = ts;
        g_part[blk * 2 + 1] = tq;
    }
}
__global__ void gn_stats2_kernel() {
    int bg = blockIdx.x * blockDim.x + threadIdx.x;
    if (bg >= Bb * GROUPS) return;
    const float cnt = (float)((Cc / GROUPS) * Nn);
    float s = 0.f, sq = 0.f;
    #pragma unroll
    for (int j = 0; j < 8; j++) {
        s  += g_part[(bg * 8 + j) * 2 + 0];
        sq += g_part[(bg * 8 + j) * 2 + 1];
    }
    float mu = s / cnt;
    float var = sq / cnt - mu * mu;
    g_stats[bg * 2 + 0] = mu;
    g_stats[bg * 2 + 1] = rsqrtf(var + EPS);
}

// ---------------- 2) GN apply + transpose -> fp16 [B,N,C] ----------------
__global__ void gn_apply_kernel(const float* __restrict__ x,
                                const float* __restrict__ w,
                                const float* __restrict__ b) {
    __shared__ float sm[32][33];
    int bz = blockIdx.z;
    int n0 = blockIdx.x * 32;
    int c0 = blockIdx.y * 32;
    int tx = threadIdx.x, ty = threadIdx.y;
    {
        int c = c0 + ty, n = n0 + tx;
        int g = c >> 6;
        float mu   = g_stats[(bz * GROUPS + g) * 2 + 0];
        float rstd = g_stats[(bz * GROUPS + g) * 2 + 1];
        float v = x[((size_t)bz * Cc + c) * Nn + n];
        sm[ty][tx] = (v - mu) * rstd * w[c] + b[c];
    }
    __syncthreads();
    {
        int n = n0 + ty, c = c0 + tx;
        size_t idx = ((size_t)bz * Nn + n) * Cc + c;
        g_hh[idx] = __float2half_rn(sm[tx][ty]);
    }
}

// weight convert: fp32 -> fp16
__global__ void cvt_kernel(const float* __restrict__ w0, const float* __restrict__ w1,
                           const float* __restrict__ w2, const float* __restrict__ w3,
                           __half* __restrict__ dh) {
    int sel = blockIdx.y;
    const float* src = (sel == 0) ? w0 : (sel == 1) ? w1 : (sel == 2) ? w2 : w3;
    int i = (blockIdx.x * 256 + threadIdx.x) * 4;
    float4 v = *(const float4*)(src + i);
    __half2 hh0 = {__float2half_rn(v.x), __float2half_rn(v.y)};
    __half2 hh1 = {__float2half_rn(v.z), __float2half_rn(v.w)};
    __half* d = dh + (size_t)sel * Cc * Cc + i;
    ((__half2*)d)[0] = hh0;
    ((__half2*)d)[1] = hh1;
}

// ---------------- tensor-core TN GEMM machinery (fp16) ----------------
#define PLB 8192
#define STGB (4 * PLB)
#define NSTAGE 3
#define TPITCH 129

__device__ __forceinline__ uint32_t cvta_s(const void* p) {
    return (uint32_t)__cvta_generic_to_shared(p);
}
__device__ __forceinline__ void cp16(uint32_t s, const void* g) {
    asm volatile("cp.async.cg.shared.global [%0], [%1], 16;" :: "r"(s), "l"(g));
}
__device__ __forceinline__ void sts128(uint32_t a, uint32_t r0, uint32_t r1, uint32_t r2, uint32_t r3) {
    asm volatile("st.shared.v4.b32 [%0], {%1,%2,%3,%4};" :: "r"(a), "r"(r0), "r"(r1), "r"(r2), "r"(r3));
}
__device__ __forceinline__ void ldsm4(uint32_t& r0, uint32_t& r1, uint32_t& r2, uint32_t& r3, uint32_t a) {
    asm volatile("ldmatrix.sync.aligned.m8n8.x4.shared.b16 {%0,%1,%2,%3}, [%4];"
                 : "=r"(r0), "=r"(r1), "=r"(r2), "=r"(r3) : "r"(a));
}
__device__ __forceinline__ void mma16816(float* c, const uint32_t* a, const uint32_t* b) {
    asm volatile("mma.sync.aligned.m16n8k16.row.col.f32.f16.f16.f32 "
                 "{%0,%1,%2,%3},{%4,%5,%6,%7},{%8,%9},{%0,%1,%2,%3};"
                 : "+f"(c[0]), "+f"(c[1]), "+f"(c[2]), "+f"(c[3])
                 : "r"(a[0]), "r"(a[1]), "r"(a[2]), "r"(a[3]), "r"(b[0]), "r"(b[1]));
}
__device__ __forceinline__ uint32_t swz(int row, int chunk) {
    return (uint32_t)(row * 64 + ((chunk ^ ((row >> 1) & 3)) << 4));
}
__device__ __forceinline__ uint32_t exp_h2(uint32_t in, float mxr) {
    __half2 h = *(__half2*)&in;
    float2 f = __half22float2(h);
    __half2 o = __floats2half2_rn(__expf(f.x - mxr), __expf(f.y - mxr));
    return *(uint32_t*)&o;
}

// C = A·B^T, plain fp16, fp32 accum (cp.async both operands)
__device__ __forceinline__ void gemm_mainloop(
    const __half* Ah, const __half* Bh,
    int brow, int bcol, int K, uint32_t sbase,
    int tid, int lane, int wm, int wn,
    float acc[2][8][4]) {

    int ldrow = tid >> 1;
    int ldc0 = (tid & 1) * 2;

    auto load_stage = [&](int slot, int k0) {
        uint32_t so = sbase + (uint32_t)(slot * STGB);
        size_t ga = (size_t)(brow + ldrow) * K + k0;
        size_t gb = (size_t)(bcol + ldrow) * K + k0;
        #pragma unroll
        for (int cc = 0; cc < 2; cc++) {
            int c = ldc0 + cc;
            uint32_t off = swz(ldrow, c);
            cp16(so + 0 * PLB + off, Ah + ga + c * 8);
            cp16(so + 2 * PLB + off, Bh + gb + c * 8);
        }
    };

    int nk = K >> 5;
    load_stage(0, 0);
    asm volatile("cp.async.commit_group;");
    load_stage(1, 32);
    asm volatile("cp.async.commit_group;");

    for (int kt = 0; kt < nk; kt++) {
        if (kt + 1 < nk) {
            asm volatile("cp.async.wait_group 1;");
        } else {
            asm volatile("cp.async.wait_group 0;");
        }
        __syncthreads();
        uint32_t so = sbase + (uint32_t)((kt % NSTAGE) * STGB);
        #pragma unroll
        for (int kk = 0; kk < 2; kk++) {
            uint32_t ah[2][4];
            int arow = wm * 32 + ((lane >> 3) & 1) * 8 + (lane & 7);
            int akof = kk * 16 + (lane >> 4) * 8;
            int achk = akof >> 3;
            #pragma unroll
            for (int mt = 0; mt < 2; mt++) {
                uint32_t addr = so + swz(arow + mt * 16, achk);
                ldsm4(ah[mt][0], ah[mt][1], ah[mt][2], ah[mt][3], addr);
            }
            uint32_t bh[8][2];
            int bphase = lane >> 3;
            int brl = wn * 64 + (lane & 7) + (bphase >> 1) * 8;
            int bkof = kk * 16 + (bphase & 1) * 8;
            int bchk = bkof >> 3;
            #pragma unroll
            for (int np = 0; np < 4; np++) {
                uint32_t addr = so + 2 * PLB + swz(brl + np * 16, bchk);
                uint32_t r0, r1, r2, r3;
                ldsm4(r0, r1, r2, r3, addr);
                bh[np * 2][0] = r0; bh[np * 2][1] = r1;
                bh[np * 2 + 1][0] = r2; bh[np * 2 + 1][1] = r3;
            }
            #pragma unroll
            for (int mt = 0; mt < 2; mt++)
                #pragma unroll
                for (int nt = 0; nt < 8; nt++)
                    mma16816(acc[mt][nt], ah[mt], bh[nt]);
        }
        if (kt + 2 < nk) {
            load_stage((kt + 2) % NSTAGE, (kt + 2) << 5);
            asm volatile("cp.async.commit_group;");
        }
    }
}

__device__ __forceinline__ void stage_acc(float* buf, float acc[2][8][4],
                                          const float* bias, int lane, int wm, int wn) {
    int gid = lane >> 2, tig = lane & 3;
    #pragma unroll
    for (int nt = 0; nt < 8; nt++) {
        int c = wn * 64 + nt * 8 + tig * 2;
        float b0 = bias ? bias[c] : 0.f;
        float b1 = bias ? bias[c + 1] : 0.f;
        #pragma unroll
        for (int mt = 0; mt < 2; mt++) {
            int r = wm * 32 + mt * 16 + gid;
            buf[r * TPITCH + c]           = acc[mt][nt][0] + b0;
            buf[r * TPITCH + c + 1]       = acc[mt][nt][1] + b1;
            buf[(r + 8) * TPITCH + c]     = acc[mt][nt][2] + b0;
            buf[(r + 8) * TPITCH + c + 1] = acc[mt][nt][3] + b1;
        }
    }
}

// ---------------- scores GEMM: writes fp16 scaled scores + per-tile row stats ----
__global__ __launch_bounds__(256, 2)
void mma_scores(const __half* __restrict__ Ah, const __half* __restrict__ Bh,
                __half* __restrict__ Ch,
                int K, float alpha) {
    extern __shared__ __half smbuf[];
    __shared__ float red_m[128][2], red_s[128][2];
    long long zb = blockIdx.z;
    Ah += zb * NCs;
    Bh += zb * NCs;
    Ch += zb * NNs;

    int tid = threadIdx.x;
    int lane = tid & 31, warp = tid >> 5;
    int wm = warp & 3, wn = warp >> 2;
    int brow = blockIdx.y * 128, bcol = blockIdx.x * 128;
    uint32_t sbase = cvta_s(smbuf);

    float acc[2][8][4];
    #pragma unroll
    for (int i = 0; i < 2; i++)
        #pragma unroll
        for (int j = 0; j < 8; j++)
            #pragma unroll
            for (int q = 0; q < 4; q++) acc[i][j][q] = 0.f;

    gemm_mainloop(Ah, Bh, brow, bcol, K, sbase, tid, lane, wm, wn, acc);

    int gid = lane >> 2, tig = lane & 3;

    // write scores + thread-local row max (per row instance: [mt][h])
    float vmax[2][2] = {{-1e30f, -1e30f}, {-1e30f, -1e30f}};
    #pragma unroll
    for (int nt = 0; nt < 8; nt++) {
        int col = bcol + wn * 64 + nt * 8 + tig * 2;
        #pragma unroll
        for (int mt = 0; mt < 2; mt++) {
            int row0 = brow + wm * 32 + mt * 16 + gid;
            float v0 = acc[mt][nt][0] * alpha;
            float v1 = acc[mt][nt][1] * alpha;
            float v2 = acc[mt][nt][2] * alpha;
            float v3 = acc[mt][nt][3] * alpha;
            vmax[mt][0] = fmaxf(vmax[mt][0], fmaxf(v0, v1));
            vmax[mt][1] = fmaxf(vmax[mt][1], fmaxf(v2, v3));
            __half2 hh0 = {__float2half_rn(v0), __float2half_rn(v1)};
            __half2 hh1 = {__float2half_rn(v2), __float2half_rn(v3)};
            *(__half2*)(Ch + (size_t)row0 * Nn + col) = hh0;
            *(__half2*)(Ch + (size_t)(row0 + 8) * Nn + col) = hh1;
        }
    }
    // reduce max over tig group
    #pragma unroll
    for (int o = 1; o <= 2; o <<= 1) {
        #pragma unroll
        for (int mt = 0; mt < 2; mt++) {
            vmax[mt][0] = fmaxf(vmax[mt][0], __shfl_xor_sync(~0u, vmax[mt][0], o));
            vmax[mt][1] = fmaxf(vmax[mt][1], __shfl_xor_sync(~0u, vmax[mt][1], o));
        }
    }
    if (tig == 0) {
        #pragma unroll
        for (int mt = 0; mt < 2; mt++) {
            red_m[wm * 32 + mt * 16 + gid][wn]     = vmax[mt][0];
            red_m[wm * 32 + mt * 16 + gid + 8][wn] = vmax[mt][1];
        }
    }
    __syncthreads();
    // tile-row max, then sum of exp
    float M[2][2];
    #pragma unroll
    for (int mt = 0; mt < 2; mt++) {
        int r0 = wm * 32 + mt * 16 + gid;
        M[mt][0] = fmaxf(red_m[r0][0], red_m[r0][1]);
        M[mt][1] = fmaxf(red_m[r0 + 8][0], red_m[r0 + 8][1]);
    }
    float vsum[2][2] = {{0.f, 0.f}, {0.f, 0.f}};
    #pragma unroll
    for (int nt = 0; nt < 8; nt++)
        #pragma unroll
        for (int mt = 0; mt < 2; mt++) {
            vsum[mt][0] += __expf(acc[mt][nt][0] * alpha - M[mt][0]);
            vsum[mt][0] += __expf(acc[mt][nt][1] * alpha - M[mt][0]);
            vsum[mt][1] += __expf(acc[mt][nt][2] * alpha - M[mt][1]);
            vsum[mt][1] += __expf(acc[mt][nt][3] * alpha - M[mt][1]);
        }
    #pragma unroll
    for (int o = 1; o <= 2; o <<= 1) {
        #pragma unroll
        for (int mt = 0; mt < 2; mt++) {
            vsum[mt][0] += __shfl_xor_sync(~0u, vsum[mt][0], o);
            vsum[mt][1] += __shfl_xor_sync(~0u, vsum[mt][1], o);
        }
    }
    if (tig == 0) {
        #pragma unroll
        for (int mt = 0; mt < 2; mt++) {
            red_s[wm * 32 + mt * 16 + gid][wn]     = vsum[mt][0];
            red_s[wm * 32 + mt * 16 + gid + 8][wn] = vsum[mt][1];
        }
    }
    __syncthreads();
    if (wn == 0 && tig == 0) {
        #pragma unroll
        for (int mt = 0; mt < 2; mt++) {
            #pragma unroll
            for (int h = 0; h < 2; h++) {
                int r = wm * 32 + mt * 16 + gid + h * 8;
                float Mf = fmaxf(red_m[r][0], red_m[r][1]);
                float Sf = red_s[r][0] + red_s[r][1];
                g_red[(size_t)blockIdx.x * NROWS + zb * Nn + brow + r] =
                    make_float2(Mf, Sf);
            }
        }
    }
}

// ---------------- combine per-tile stats -> row max + 1/sum ----------------
__global__ void rowstats_kernel() {
    int idx = blockIdx.x * 256 + threadIdx.x;   // 0..32767
    float M = -1e30f;
    #pragma unroll 4
    for (int i = 0; i < 32; i++)
        M = fmaxf(M, g_red[(size_t)i * NROWS + idx].x);
    float S = 0.f;
    #pragma unroll 4
    for (int i = 0; i < 32; i++) {
        float2 p = g_red[(size_t)i * NROWS + idx];
        S += p.y * __expf(p.x - M);
    }
    g_mx[idx] = M;
    g_inv[idx] = 1.f / S;
}

// ---------------- PV GEMM: A = exp(scores - mx) on the fly; epilogue x inv ----
__global__ __launch_bounds__(256, 2)
void mma_pv(const __half* __restrict__ S, const __half* __restrict__ Vt,
            __half* __restrict__ Ch) {
    extern __shared__ __half smbuf[];
    long long zb = blockIdx.z;
    S  += zb * NNs;
    Vt += zb * NCs;
    Ch += zb * NCs;
    const int K = Nn;

    int tid = threadIdx.x;
    int lane = tid & 31, warp = tid >> 5;
    int wm = warp & 3, wn = warp >> 2;
    int brow = blockIdx.y * 128, bcol = blockIdx.x * 128;
    uint32_t sbase = cvta_s(smbuf);

    int ldrow = tid >> 1;
    int ldc0 = (tid & 1) * 2;
    float mxr = g_mx[zb * Nn + brow + ldrow];

    float acc[2][8][4];
    #pragma unroll
    for (int i = 0; i < 2; i++)
        #pragma unroll
        for (int j = 0; j < 8; j++)
            #pragma unroll
            for (int q = 0; q < 4; q++) acc[i][j][q] = 0.f;

    auto load_stage = [&](int slot, int k0) {
        uint32_t so = sbase + (uint32_t)(slot * STGB);
        // A: ldg scores, exp, STS
        const __half* ga = S + (size_t)(brow + ldrow) * K + k0 + ldc0 * 8;
        uint4 d0 = *(const uint4*)(ga);
        uint4 d1 = *(const uint4*)(ga + 8);
        // B: cp.async Vt
        size_t gb = (size_t)(bcol + ldrow) * K + k0;
        cp16(so + 2 * PLB + swz(ldrow, ldc0),     Vt + gb + ldc0 * 8);
        cp16(so + 2 * PLB + swz(ldrow, ldc0 + 1), Vt + gb + (ldc0 + 1) * 8);
        // exp + store A
        uint32_t e0 = exp_h2(d0.x, mxr), e1 = exp_h2(d0.y, mxr);
        uint32_t e2 = exp_h2(d0.z, mxr), e3 = exp_h2(d0.w, mxr);
        sts128(so + swz(ldrow, ldc0), e0, e1, e2, e3);
        e0 = exp_h2(d1.x, mxr); e1 = exp_h2(d1.y, mxr);
        e2 = exp_h2(d1.z, mxr); e3 = exp_h2(d1.w, mxr);
        sts128(so + swz(ldrow, ldc0 + 1), e0, e1, e2, e3);
    };

    int nk = K >> 5;
    load_stage(0, 0);
    asm volatile("cp.async.commit_group;");
    load_stage(1, 32);
    asm volatile("cp.async.commit_group;");

    for (int kt = 0; kt < nk; kt++) {
        if (kt + 1 < nk) {
            asm volatile("cp.async.wait_group 1;");
        } else {
            asm volatile("cp.async.wait_group 0;");
        }
        __syncthreads();
        uint32_t so = sbase + (uint32_t)((kt % NSTAGE) * STGB);
        #pragma unroll
        for (int kk = 0; kk < 2; kk++) {
            uint32_t ah[2][4];
            int arow = wm * 32 + ((lane >> 3) & 1) * 8 + (lane & 7);
            int akof = kk * 16 + (lane >> 4) * 8;
            int achk = akof >> 3;
            #pragma unroll
            for (int mt = 0; mt < 2; mt++) {
                uint32_t addr = so + swz(arow + mt * 16, achk);
                ldsm4(ah[mt][0], ah[mt][1], ah[mt][2], ah[mt][3], addr);
            }
            uint32_t bh[8][2];
            int bphase = lane >> 3;
            int brl = wn * 64 + (lane & 7) + (bphase >> 1) * 8;
            int bkof = kk * 16 + (bphase & 1) * 8;
            int bchk = bkof >> 3;
            #pragma unroll
            for (int np = 0; np < 4; np++) {
                uint32_t addr = so + 2 * PLB + swz(brl + np * 16, bchk);
                uint32_t r0, r1, r2, r3;
                ldsm4(r0, r1, r2, r3, addr);
                bh[np * 2][0] = r0; bh[np * 2][1] = r1;
                bh[np * 2 + 1][0] = r2; bh[np * 2 + 1][1] = r3;
            }
            #pragma unroll
            for (int mt = 0; mt < 2; mt++)
                #pragma unroll
                for (int nt = 0; nt < 8; nt++)
                    mma16816(acc[mt][nt], ah[mt], bh[nt]);
        }
        if (kt + 2 < nk) {
            load_stage((kt + 2) % NSTAGE, (kt + 2) << 5);
            asm volatile("cp.async.commit_group;");
        }
    }

    int gid = lane >> 2, tig = lane & 3;
    float invr[2][2];
    #pragma unroll
    for (int mt = 0; mt < 2; mt++) {
        int r0 = brow + wm * 32 + mt * 16 + gid;
        invr[mt][0] = g_inv[zb * Nn + r0];
        invr[mt][1] = g_inv[zb * Nn + r0 + 8];
    }
    #pragma unroll
    for (int nt = 0; nt < 8; nt++) {
        int col = bcol + wn * 64 + nt * 8 + tig * 2;
        #pragma unroll
        for (int mt = 0; mt < 2; mt++) {
            int row0 = brow + wm * 32 + mt * 16 + gid;
            __half2 hh0 = {__float2half_rn(acc[mt][nt][0] * invr[mt][0]),
                           __float2half_rn(acc[mt][nt][1] * invr[mt][0])};
            __half2 hh1 = {__float2half_rn(acc[mt][nt][2] * invr[mt][1]),
                           __float2half_rn(acc[mt][nt][3] * invr[mt][1])};
            *(__half2*)(Ch + (size_t)row0 * Cc + col) = hh0;
            *(__half2*)(Ch + (size_t)(row0 + 8) * Cc + col) = hh1;
        }
    }
}

// fused QKV projection (1-term); Q, K, V^T(via transpose) fp16.
__global__ __launch_bounds__(256, 2)
void mma_qkv(const __half* __restrict__ Ah, const __half* __restrict__ Bh,
             const float* __restrict__ bq, const float* __restrict__ bk,
             const float* __restrict__ bv,
             __half* __restrict__ Qh,
             __half* __restrict__ Kh,
             __half* __restrict__ Vth,
             int K) {
    extern __shared__ __half smbuf[];
    int tid = threadIdx.x;
    int lane = tid & 31, warp = tid >> 5;
    int wm = warp & 3, wn = warp >> 2;
    int brow = blockIdx.y * 128, bcol = blockIdx.x * 128;
    uint32_t sbase = cvta_s(smbuf);

    float acc[2][8][4];
    #pragma unroll
    for (int i = 0; i < 2; i++)
        #pragma unroll
        for (int j = 0; j < 8; j++)
            #pragma unroll
            for (int q = 0; q < 4; q++) acc[i][j][q] = 0.f;

    gemm_mainloop(Ah, Bh, brow, bcol, K, sbase, tid, lane, wm, wn, acc);

    int sec = bcol >> 9;            // 0=q 1=k 2=v
    int colbase = bcol & 511;

    if (sec == 2) {
        __syncthreads();
        float* buf = (float*)smbuf;
        stage_acc(buf, acc, bv + colbase, lane, wm, wn);
        __syncthreads();
        int d = tid >> 1, mh = tid & 1;
        int b = brow >> 12, m0 = (brow & 4095) + mh * 64;
        size_t base = ((size_t)b * Cc + colbase + d) * Nn + m0;
        #pragma unroll 8
        for (int i = 0; i < 32; i++) {
            float f0 = buf[(mh * 64 + 2 * i) * TPITCH + d];
            float f1 = buf[(mh * 64 + 2 * i + 1) * TPITCH + d];
            __half2 hh = {__float2half_rn(f0), __float2half_rn(f1)};
            *(__half2*)(Vth + base + 2 * i) = hh;
        }
        return;
    }

    const float* bias = (sec == 0) ? bq : bk;
    __half* Ch = (sec == 0) ? Qh : Kh;
    int gid = lane >> 2, tig = lane & 3;
    #pragma unroll
    for (int nt = 0; nt < 8; nt++) {
        int col = colbase + wn * 64 + nt * 8 + tig * 2;
        float b0 = bias[col], b1 = bias[col + 1];
        #pragma unroll
        for (int mt = 0; mt < 2; mt++) {
            int row0 = brow + wm * 32 + mt * 16 + gid;
            __half2 hh0 = {__float2half_rn(acc[mt][nt][0] + b0),
                           __float2half_rn(acc[mt][nt][1] + b1)};
            __half2 hh1 = {__float2half_rn(acc[mt][nt][2] + b0),
                           __float2half_rn(acc[mt][nt][3] + b1)};
            *(__half2*)(Ch + (size_t)row0 * Cc + col) = hh0;
            *(__half2*)(Ch + (size_t)(row0 + 8) * Cc + col) = hh1;
        }
    }
}

// final projection (1-term) fused with residual + transpose-back
__global__ __launch_bounds__(256, 2)
void mma_resid(const __half* __restrict__ Ah, const __half* __restrict__ Bh,
               const float* __restrict__ bias,
               const float* __restrict__ x, float* __restrict__ out,
               int K) {
    extern __shared__ __half smbuf[];
    int tid = threadIdx.x;
    int lane = tid & 31, warp = tid >> 5;
    int wm = warp & 3, wn = warp >> 2;
    int brow = blockIdx.y * 128, bcol = blockIdx.x * 128;
    uint32_t sbase = cvta_s(smbuf);

    float acc[2][8][4];
    #pragma unroll
    for (int i = 0; i < 2; i++)
        #pragma unroll
        for (int j = 0; j < 8; j++)
            #pragma unroll
            for (int q = 0; q < 4; q++) acc[i][j][q] = 0.f;

    gemm_mainloop(Ah, Bh, brow, bcol, K, sbase, tid, lane, wm, wn, acc);

    __syncthreads();
    float* buf = (float*)smbuf;
    stage_acc(buf, acc, bias + bcol, lane, wm, wn);
    __syncthreads();

    int c = tid >> 1, nh = tid & 1;
    int b = brow >> 12, n0 = (brow & 4095) + nh * 64;
    size_t base = ((size_t)b * Cc + bcol + c) * Nn + n0;
    #pragma unroll
    for (int i = 0; i < 16; i++) {
        float4 xv = *(const float4*)(x + base + 4 * i);
        float4 o;
        o.x = xv.x + buf[(nh * 64 + 4 * i + 0) * TPITCH + c];
        o.y = xv.y + buf[(nh * 64 + 4 * i + 1) * TPITCH + c];
        o.z = xv.z + buf[(nh * 64 + 4 * i + 2) * TPITCH + c];
        o.w = xv.w + buf[(nh * 64 + 4 * i + 3) * TPITCH + c];
        *(float4*)(out + base + 4 * i) = o;
    }
}

// ---------------- launch ----------------
extern "C" void kernel_launch(void* const* d_in, const int* in_sizes, int n_in,
                              void* d_out, int out_size) {
    const float* x    = (const float*)d_in[0];
    const float* gn_w = (const float*)d_in[1];
    const float* gn_b = (const float*)d_in[2];
    const float* wq   = (const float*)d_in[3];
    const float* bq   = (const float*)d_in[4];
    const float* wk   = (const float*)d_in[5];
    const float* bk   = (const float*)d_in[6];
    const float* wv   = (const float*)d_in[7];
    const float* bv   = (const float*)d_in[8];
    const float* wo   = (const float*)d_in[9];
    const float* bo   = (const float*)d_in[10];
    float* out = (float*)d_out;

    __half *hh, *w4h, *qh, *kh, *vth, *sh, *aoh;
    cudaGetSymbolAddress((void**)&hh, g_hh);
    cudaGetSymbolAddress((void**)&w4h, g_w4h);
    cudaGetSymbolAddress((void**)&qh, g_qh);
    cudaGetSymbolAddress((void**)&kh, g_kh);
    cudaGetSymbolAddress((void**)&vth, g_vth);
    cudaGetSymbolAddress((void**)&sh, g_sh);
    cudaGetSymbolAddress((void**)&aoh, g_aoh);

    const int Mtot = Bb * Nn;                        // 32768
    const float scale = 0.044194173824159216f;       // 1/sqrt(512)
    const int WSZ = Cc * Cc;                         // 262144
    const int SMEM = NSTAGE * STGB;                  // 96 KB

    cudaFuncSetAttribute(mma_scores, cudaFuncAttributeMaxDynamicSharedMemorySize, SMEM);
    cudaFuncSetAttribute(mma_pv, cudaFuncAttributeMaxDynamicSharedMemorySize, SMEM);
    cudaFuncSetAttribute(mma_qkv, cudaFuncAttributeMaxDynamicSharedMemorySize, SMEM);
    cudaFuncSetAttribute(mma_resid, cudaFuncAttributeMaxDynamicSharedMemorySize, SMEM);

    gn_stats1_kernel<<<512, 256>>>(x);
    gn_stats2_kernel<<<2, 32>>>();
    gn_apply_kernel<<<dim3(Nn / 32, Cc / 32, Bb), dim3(32, 32)>>>(x, gn_w, gn_b);
    cvt_kernel<<<dim3(WSZ / 1024, 4), 256>>>(wq, wk, wv, wo, w4h);

    // fused QKV projection (1-term fp16)
    mma_qkv<<<dim3(12, Mtot / 128), 256, SMEM>>>(hh, w4h,
                                                 bq, bk, bv, qh, kh, vth, Cc);
    // scores = q k^T * scale  (fp16 out + per-tile row stats)
    mma_scores<<<dim3(Nn / 128, Nn / 128, Bb), 256, SMEM>>>(qh, kh, sh, Cc, scale);
    // combine stats -> row max + 1/sum
    rowstats_kernel<<<NROWS / 256, 256>>>();
    // attn out = exp(S - mx) @ V, normalized in epilogue
    mma_pv<<<dim3(Cc / 128, Nn / 128, Bb), 256, SMEM>>>(sh, vth, aoh);
    // final projection + residual + transpose-back
    mma_resid<<<dim3(Cc / 128, Mtot / 128), 256, SMEM>>>(aoh,
                                 w4h + 3 * WSZ, bo, x, out, Cc);
}

// round 16
// speedup vs baseline: 1.1028x; 1.1028x over previous
#include <cuda_runtime.h>
#include <cuda_fp16.h>
#include <math.h>
#include <stdint.h>

#define Cc 512
#define Bb 8
#define Nn 4096
#define GROUPS 8
#define EPS 1e-5f

#define MC ((size_t)Bb * Nn * Cc)
#define SC ((size_t)Bb * Nn * Nn)
#define NCs ((long long)Nn * Cc)
#define NNs ((long long)Nn * Nn)

// ---------------- scratch ----------------
__device__ __half g_hh[MC];
__device__ __half g_w4h[4 * Cc * Cc];
__device__ __half g_qh[MC];
__device__ __half g_kh[MC];
__device__ __half g_vth[MC];
__device__ __half g_sh[SC];            // scores fp16 (scaled)
__device__ __half g_ph[SC];            // probs fp16
__device__ __half g_aoh[MC];
__device__ float  g_stats[Bb * GROUPS * 2];
__device__ float  g_part[512 * 2];

// ---------------- 1) group-norm statistics (two-phase) ----------------
__global__ void gn_stats1_kernel(const float* __restrict__ x) {
    int blk = blockIdx.x;
    int bg = blk >> 3, sub = blk & 7;
    const size_t cnt = (size_t)(Cc / GROUPS) * Nn;
    const float4* p = (const float4*)(x + (size_t)bg * cnt + (size_t)sub * (cnt / 8));
    int tid = threadIdx.x;
    float s = 0.f, sq = 0.f;
    #pragma unroll 4
    for (int i = tid; i < (int)(cnt / 8 / 4); i += 256) {
        float4 v = p[i];
        s  += v.x + v.y + v.z + v.w;
        sq += v.x * v.x + v.y * v.y + v.z * v.z + v.w * v.w;
    }
    int lane = tid & 31, warp = tid >> 5;
    #pragma unroll
    for (int o = 16; o > 0; o >>= 1) {
        s  += __shfl_xor_sync(~0u, s, o);
        sq += __shfl_xor_sync(~0u, sq, o);
    }
    __shared__ float ss[8], ssq[8];
    if (lane == 0) { ss[warp] = s; ssq[warp] = sq; }
    __syncthreads();
    if (tid == 0) {
        float ts = 0.f, tq = 0.f;
        #pragma unroll
        for (int j = 0; j < 8; j++) { ts += ss[j]; tq += ssq[j]; }
        g_part[blk * 2 + 0] = ts;
        g_part[blk * 2 + 1] = tq;
    }
}
__global__ void gn_stats2_kernel() {
    int bg = blockIdx.x * blockDim.x + threadIdx.x;
    if (bg >= Bb * GROUPS) return;
    const float cnt = (float)((Cc / GROUPS) * Nn);
    float s = 0.f, sq = 0.f;
    #pragma unroll
    for (int j = 0; j < 8; j++) {
        s  += g_part[(bg * 8 + j) * 2 + 0];
        sq += g_part[(bg * 8 + j) * 2 + 1];
    }
    float mu = s / cnt;
    float var = sq / cnt - mu * mu;
    g_stats[bg * 2 + 0] = mu;
    g_stats[bg * 2 + 1] = rsqrtf(var + EPS);
}

// ---------------- 2) GN apply + transpose -> fp16 [B,N,C] ----------------
__global__ void gn_apply_kernel(const float* __restrict__ x,
                                const float* __restrict__ w,
                                const float* __restrict__ b) {
    __shared__ float sm[32][33];
    int bz = blockIdx.z;
    int n0 = blockIdx.x * 32;
    int c0 = blockIdx.y * 32;
    int tx = threadIdx.x, ty = threadIdx.y;
    {
        int c = c0 + ty, n = n0 + tx;
        int g = c >> 6;
        float mu   = g_stats[(bz * GROUPS + g) * 2 + 0];
        float rstd = g_stats[(bz * GROUPS + g) * 2 + 1];
        float v = x[((size_t)bz * Cc + c) * Nn + n];
        sm[ty][tx] = (v - mu) * rstd * w[c] + b[c];
    }
    __syncthreads();
    {
        int n = n0 + ty, c = c0 + tx;
        size_t idx = ((size_t)bz * Nn + n) * Cc + c;
        g_hh[idx] = __float2half_rn(sm[tx][ty]);
    }
}

// weight convert: fp32 -> fp16
__global__ void cvt_kernel(const float* __restrict__ w0, const float* __restrict__ w1,
                           const float* __restrict__ w2, const float* __restrict__ w3,
                           __half* __restrict__ dh) {
    int sel = blockIdx.y;
    const float* src = (sel == 0) ? w0 : (sel == 1) ? w1 : (sel == 2) ? w2 : w3;
    int i = (blockIdx.x * 256 + threadIdx.x) * 4;
    float4 v = *(const float4*)(src + i);
    __half2 hh0 = {__float2half_rn(v.x), __float2half_rn(v.y)};
    __half2 hh1 = {__float2half_rn(v.z), __float2half_rn(v.w)};
    __half* d = dh + (size_t)sel * Cc * Cc + i;
    ((__half2*)d)[0] = hh0;
    ((__half2*)d)[1] = hh1;
}

// ---------------- tensor-core TN GEMM machinery (fp16) ----------------
#define PLB 8192
#define STGB (4 * PLB)
#define NSTAGE 3
#define TPITCH 129

__device__ __forceinline__ uint32_t cvta_s(const void* p) {
    return (uint32_t)__cvta_generic_to_shared(p);
}
__device__ __forceinline__ void cp16(uint32_t s, const void* g) {
    asm volatile("cp.async.cg.shared.global [%0], [%1], 16;" :: "r"(s), "l"(g));
}
__device__ __forceinline__ void ldsm4(uint32_t& r0, uint32_t& r1, uint32_t& r2, uint32_t& r3, uint32_t a) {
    asm volatile("ldmatrix.sync.aligned.m8n8.x4.shared.b16 {%0,%1,%2,%3}, [%4];"
                 : "=r"(r0), "=r"(r1), "=r"(r2), "=r"(r3) : "r"(a));
}
__device__ __forceinline__ void mma16816(float* c, const uint32_t* a, const uint32_t* b) {
    asm volatile("mma.sync.aligned.m16n8k16.row.col.f32.f16.f16.f32 "
                 "{%0,%1,%2,%3},{%4,%5,%6,%7},{%8,%9},{%0,%1,%2,%3};"
                 : "+f"(c[0]), "+f"(c[1]), "+f"(c[2]), "+f"(c[3])
                 : "r"(a[0]), "r"(a[1]), "r"(a[2]), "r"(a[3]), "r"(b[0]), "r"(b[1]));
}
__device__ __forceinline__ uint32_t swz(int row, int chunk) {
    return (uint32_t)(row * 64 + ((chunk ^ ((row >> 1) & 3)) << 4));
}

// C = A·B^T, plain fp16, fp32 accum
__device__ __forceinline__ void gemm_mainloop(
    const __half* Ah, const __half* Bh,
    int brow, int bcol, int K, uint32_t sbase,
    int tid, int lane, int wm, int wn,
    float acc[2][8][4]) {

    int ldrow = tid >> 1;
    int ldc0 = (tid & 1) * 2;

    auto load_stage = [&](int slot, int k0) {
        uint32_t so = sbase + (uint32_t)(slot * STGB);
        size_t ga = (size_t)(brow + ldrow) * K + k0;
        size_t gb = (size_t)(bcol + ldrow) * K + k0;
        #pragma unroll
        for (int cc = 0; cc < 2; cc++) {
            int c = ldc0 + cc;
            uint32_t off = swz(ldrow, c);
            cp16(so + 0 * PLB + off, Ah + ga + c * 8);
            cp16(so + 2 * PLB + off, Bh + gb + c * 8);
        }
    };

    int nk = K >> 5;
    load_stage(0, 0);
    asm volatile("cp.async.commit_group;");
    load_stage(1, 32);
    asm volatile("cp.async.commit_group;");

    for (int kt = 0; kt < nk; kt++) {
        if (kt + 1 < nk) {
            asm volatile("cp.async.wait_group 1;");
        } else {
            asm volatile("cp.async.wait_group 0;");
        }
        __syncthreads();
        uint32_t so = sbase + (uint32_t)((kt % NSTAGE) * STGB);
        #pragma unroll
        for (int kk = 0; kk < 2; kk++) {
            uint32_t ah[2][4];
            int arow = wm * 32 + ((lane >> 3) & 1) * 8 + (lane & 7);
            int akof = kk * 16 + (lane >> 4) * 8;
            int achk = akof >> 3;
            #pragma unroll
            for (int mt = 0; mt < 2; mt++) {
                uint32_t addr = so + swz(arow + mt * 16, achk);
                ldsm4(ah[mt][0], ah[mt][1], ah[mt][2], ah[mt][3], addr);
            }
            uint32_t bh[8][2];
            int bphase = lane >> 3;
            int brl = wn * 64 + (lane & 7) + (bphase >> 1) * 8;
            int bkof = kk * 16 + (bphase & 1) * 8;
            int bchk = bkof >> 3;
            #pragma unroll
            for (int np = 0; np < 4; np++) {
                uint32_t addr = so + 2 * PLB + swz(brl + np * 16, bchk);
                uint32_t r0, r1, r2, r3;
                ldsm4(r0, r1, r2, r3, addr);
                bh[np * 2][0] = r0; bh[np * 2][1] = r1;
                bh[np * 2 + 1][0] = r2; bh[np * 2 + 1][1] = r3;
            }
            #pragma unroll
            for (int mt = 0; mt < 2; mt++)
                #pragma unroll
                for (int nt = 0; nt < 8; nt++)
                    mma16816(acc[mt][nt], ah[mt], bh[nt]);
        }
        if (kt + 2 < nk) {
            load_stage((kt + 2) % NSTAGE, (kt + 2) << 5);
            asm volatile("cp.async.commit_group;");
        }
    }
}

__device__ __forceinline__ void stage_acc(float* buf, float acc[2][8][4],
                                          const float* bias, int lane, int wm, int wn) {
    int gid = lane >> 2, tig = lane & 3;
    #pragma unroll
    for (int nt = 0; nt < 8; nt++) {
        int c = wn * 64 + nt * 8 + tig * 2;
        float b0 = bias ? bias[c] : 0.f;
        float b1 = bias ? bias[c + 1] : 0.f;
        #pragma unroll
        for (int mt = 0; mt < 2; mt++) {
            int r = wm * 32 + mt * 16 + gid;
            buf[r * TPITCH + c]           = acc[mt][nt][0] + b0;
            buf[r * TPITCH + c + 1]       = acc[mt][nt][1] + b1;
            buf[(r + 8) * TPITCH + c]     = acc[mt][nt][2] + b0;
            buf[(r + 8) * TPITCH + c + 1] = acc[mt][nt][3] + b1;
        }
    }
}

// generic TN GEMM; fp16 output
__global__ __launch_bounds__(256, 2)
void mma_tn(const __half* __restrict__ Ah, const __half* __restrict__ Bh,
            __half* __restrict__ Ch,
            int M, int N, int K, float alpha,
            long long sA, long long sB, long long sC) {
    extern __shared__ __half smbuf[];
    long long zb = blockIdx.z;
    Ah += zb * sA;
    Bh += zb * sB;
    Ch += zb * sC;

    int tid = threadIdx.x;
    int lane = tid & 31, warp = tid >> 5;
    int wm = warp & 3, wn = warp >> 2;
    int brow = blockIdx.y * 128, bcol = blockIdx.x * 128;
    uint32_t sbase = cvta_s(smbuf);

    float acc[2][8][4];
    #pragma unroll
    for (int i = 0; i < 2; i++)
        #pragma unroll
        for (int j = 0; j < 8; j++)
            #pragma unroll
            for (int q = 0; q < 4; q++) acc[i][j][q] = 0.f;

    gemm_mainloop(Ah, Bh, brow, bcol, K, sbase, tid, lane, wm, wn, acc);

    int gid = lane >> 2, tig = lane & 3;
    #pragma unroll
    for (int nt = 0; nt < 8; nt++) {
        int col = bcol + wn * 64 + nt * 8 + tig * 2;
        #pragma unroll
        for (int mt = 0; mt < 2; mt++) {
            int row0 = brow + wm * 32 + mt * 16 + gid;
            __half2 hh0 = {__float2half_rn(acc[mt][nt][0] * alpha),
                           __float2half_rn(acc[mt][nt][1] * alpha)};
            __half2 hh1 = {__float2half_rn(acc[mt][nt][2] * alpha),
                           __float2half_rn(acc[mt][nt][3] * alpha)};
            *(__half2*)(Ch + (size_t)row0 * N + col) = hh0;
            *(__half2*)(Ch + (size_t)(row0 + 8) * N + col) = hh1;
        }
    }
}

// fused QKV projection (1-term); Q, K, V^T(via transpose) fp16.
__global__ __launch_bounds__(256, 2)
void mma_qkv(const __half* __restrict__ Ah, const __half* __restrict__ Bh,
             const float* __restrict__ bq, const float* __restrict__ bk,
             const float* __restrict__ bv,
             __half* __restrict__ Qh,
             __half* __restrict__ Kh,
             __half* __restrict__ Vth,
             int K) {
    extern __shared__ __half smbuf[];
    int tid = threadIdx.x;
    int lane = tid & 31, warp = tid >> 5;
    int wm = warp & 3, wn = warp >> 2;
    int brow = blockIdx.y * 128, bcol = blockIdx.x * 128;
    uint32_t sbase = cvta_s(smbuf);

    float acc[2][8][4];
    #pragma unroll
    for (int i = 0; i < 2; i++)
        #pragma unroll
        for (int j = 0; j < 8; j++)
            #pragma unroll
            for (int q = 0; q < 4; q++) acc[i][j][q] = 0.f;

    gemm_mainloop(Ah, Bh, brow, bcol, K, sbase, tid, lane, wm, wn, acc);

    int sec = bcol >> 9;            // 0=q 1=k 2=v
    int colbase = bcol & 511;

    if (sec == 2) {
        __syncthreads();
        float* buf = (float*)smbuf;
        stage_acc(buf, acc, bv + colbase, lane, wm, wn);
        __syncthreads();
        int d = tid >> 1, mh = tid & 1;
        int b = brow >> 12, m0 = (brow & 4095) + mh * 64;
        size_t base = ((size_t)b * Cc + colbase + d) * Nn + m0;
        #pragma unroll 8
        for (int i = 0; i < 32; i++) {
            float f0 = buf[(mh * 64 + 2 * i) * TPITCH + d];
            float f1 = buf[(mh * 64 + 2 * i + 1) * TPITCH + d];
            __half2 hh = {__float2half_rn(f0), __float2half_rn(f1)};
            *(__half2*)(Vth + base + 2 * i) = hh;
        }
        return;
    }

    const float* bias = (sec == 0) ? bq : bk;
    __half* Ch = (sec == 0) ? Qh : Kh;
    int gid = lane >> 2, tig = lane & 3;
    #pragma unroll
    for (int nt = 0; nt < 8; nt++) {
        int col = colbase + wn * 64 + nt * 8 + tig * 2;
        float b0 = bias[col], b1 = bias[col + 1];
        #pragma unroll
        for (int mt = 0; mt < 2; mt++) {
            int row0 = brow + wm * 32 + mt * 16 + gid;
            __half2 hh0 = {__float2half_rn(acc[mt][nt][0] + b0),
                           __float2half_rn(acc[mt][nt][1] + b1)};
            __half2 hh1 = {__float2half_rn(acc[mt][nt][2] + b0),
                           __float2half_rn(acc[mt][nt][3] + b1)};
            *(__half2*)(Ch + (size_t)row0 * Cc + col) = hh0;
            *(__half2*)(Ch + (size_t)(row0 + 8) * Cc + col) = hh1;
        }
    }
}

// final projection (1-term) fused with residual + transpose-back
__global__ __launch_bounds__(256, 2)
void mma_resid(const __half* __restrict__ Ah, const __half* __restrict__ Bh,
               const float* __restrict__ bias,
               const float* __restrict__ x, float* __restrict__ out,
               int K) {
    extern __shared__ __half smbuf[];
    int tid = threadIdx.x;
    int lane = tid & 31, warp = tid >> 5;
    int wm = warp & 3, wn = warp >> 2;
    int brow = blockIdx.y * 128, bcol = blockIdx.x * 128;
    uint32_t sbase = cvta_s(smbuf);

    float acc[2][8][4];
    #pragma unroll
    for (int i = 0; i < 2; i++)
        #pragma unroll
        for (int j = 0; j < 8; j++)
            #pragma unroll
            for (int q = 0; q < 4; q++) acc[i][j][q] = 0.f;

    gemm_mainloop(Ah, Bh, brow, bcol, K, sbase, tid, lane, wm, wn, acc);

    __syncthreads();
    float* buf = (float*)smbuf;
    stage_acc(buf, acc, bias + bcol, lane, wm, wn);
    __syncthreads();

    int c = tid >> 1, nh = tid & 1;
    int b = brow >> 12, n0 = (brow & 4095) + nh * 64;
    size_t base = ((size_t)b * Cc + bcol + c) * Nn + n0;
    #pragma unroll
    for (int i = 0; i < 16; i++) {
        float4 xv = *(const float4*)(x + base + 4 * i);
        float4 o;
        o.x = xv.x + buf[(nh * 64 + 4 * i + 0) * TPITCH + c];
        o.y = xv.y + buf[(nh * 64 + 4 * i + 1) * TPITCH + c];
        o.z = xv.z + buf[(nh * 64 + 4 * i + 2) * TPITCH + c];
        o.w = xv.w + buf[(nh * 64 + 4 * i + 3) * TPITCH + c];
        *(float4*)(out + base + 4 * i) = o;
    }
}

// ---------------- softmax rows (fp16 in/out, h2exp) ----------------
__global__ void softmax_kernel() {
    size_t row = blockIdx.x;
    __half2* p = (__half2*)(g_sh + row * Nn);
    __half2* q = (__half2*)(g_ph + row * Nn);
    int tid = threadIdx.x;
    int lane = tid & 31, warp = tid >> 5;
    __shared__ float sm1[8], sm2[8];
    __half2 v[8];
    __half2 m2 = {__float2half_rn(-60000.f), __float2half_rn(-60000.f)};
    #pragma unroll
    for (int i = 0; i < 8; i++) {
        v[i] = p[tid + i * 256];
        m2 = __hmax2(m2, v[i]);
    }
    float mx = fmaxf(__half2float(__low2half(m2)), __half2float(__high2half(m2)));
    #pragma unroll
    for (int o = 16; o > 0; o >>= 1) mx = fmaxf(mx, __shfl_xor_sync(~0u, mx, o));
    if (lane == 0) sm1[warp] = mx;
    __syncthreads();
    mx = sm1[0];
    #pragma unroll
    for (int j = 1; j < 8; j++) mx = fmaxf(mx, sm1[j]);

    __half2 hmx = __float2half2_rn(mx);
    float s = 0.f;
    #pragma unroll
    for (int i = 0; i < 8; i++) {
        v[i] = h2exp(__hsub2(v[i], hmx));
        float2 f = __half22float2(v[i]);
        s += f.x + f.y;
    }
    #pragma unroll
    for (int o = 16; o > 0; o >>= 1) s += __shfl_xor_sync(~0u, s, o);
    if (lane == 0) sm2[warp] = s;
    __syncthreads();
    s = 0.f;
    #pragma unroll
    for (int j = 0; j < 8; j++) s += sm2[j];
    __half2 hinv = __float2half2_rn(1.f / s);

    #pragma unroll
    for (int i = 0; i < 8; i++)
        q[tid + i * 256] = __hmul2(v[i], hinv);
}

// ---------------- launch ----------------
extern "C" void kernel_launch(void* const* d_in, const int* in_sizes, int n_in,
                              void* d_out, int out_size) {
    const float* x    = (const float*)d_in[0];
    const float* gn_w = (const float*)d_in[1];
    const float* gn_b = (const float*)d_in[2];
    const float* wq   = (const float*)d_in[3];
    const float* bq   = (const float*)d_in[4];
    const float* wk   = (const float*)d_in[5];
    const float* bk   = (const float*)d_in[6];
    const float* wv   = (const float*)d_in[7];
    const float* bv   = (const float*)d_in[8];
    const float* wo   = (const float*)d_in[9];
    const float* bo   = (const float*)d_in[10];
    float* out = (float*)d_out;

    __half *hh, *w4h, *qh, *kh, *vth, *sh, *ph, *aoh;
    cudaGetSymbolAddress((void**)&hh, g_hh);
    cudaGetSymbolAddress((void**)&w4h, g_w4h);
    cudaGetSymbolAddress((void**)&qh, g_qh);
    cudaGetSymbolAddress((void**)&kh, g_kh);
    cudaGetSymbolAddress((void**)&vth, g_vth);
    cudaGetSymbolAddress((void**)&sh, g_sh);
    cudaGetSymbolAddress((void**)&ph, g_ph);
    cudaGetSymbolAddress((void**)&aoh, g_aoh);

    const int Mtot = Bb * Nn;                        // 32768
    const float scale = 0.044194173824159216f;       // 1/sqrt(512)
    const int WSZ = Cc * Cc;                         // 262144
    const int SMEM = NSTAGE * STGB;                  // 96 KB

    cudaFuncSetAttribute(mma_tn, cudaFuncAttributeMaxDynamicSharedMemorySize, SMEM);
    cudaFuncSetAttribute(mma_qkv, cudaFuncAttributeMaxDynamicSharedMemorySize, SMEM);
    cudaFuncSetAttribute(mma_resid, cudaFuncAttributeMaxDynamicSharedMemorySize, SMEM);

    gn_stats1_kernel<<<512, 256>>>(x);
    gn_stats2_kernel<<<2, 32>>>();
    gn_apply_kernel<<<dim3(Nn / 32, Cc / 32, Bb), dim3(32, 32)>>>(x, gn_w, gn_b);
    cvt_kernel<<<dim3(WSZ / 1024, 4), 256>>>(wq, wk, wv, wo, w4h);

    // fused QKV projection (1-term fp16)
    mma_qkv<<<dim3(12, Mtot / 128), 256, SMEM>>>(hh, w4h,
                                                 bq, bk, bv, qh, kh, vth, Cc);
    // scores = q k^T * scale  (fp16 out)
    mma_tn<<<dim3(Nn / 128, Nn / 128, Bb), 256, SMEM>>>(qh, kh,
                                 sh, Nn, Nn, Cc, scale, NCs, NCs, NNs);
    softmax_kernel<<<Bb * Nn, 256>>>();
    // attn out = P @ V
    mma_tn<<<dim3(Cc / 128, Nn / 128, Bb), 256, SMEM>>>(ph, vth,
                                 aoh, Nn, Cc, Nn, 1.f, NNs, NCs, NCs);
    // final projection + residual + transpose-back
    mma_resid<<<dim3(Cc / 128, Mtot / 128), 256, SMEM>>>(aoh,
                                 w4h + 3 * WSZ, bo, x, out, Cc);
}